// round 1
// baseline (speedup 1.0000x reference)
#include <cuda_runtime.h>
#include <math.h>

static constexpr int kT = 512;
static constexpr int kB = 64;
static constexpr int kI = 1024;
static constexpr int kH = 1024;
static constexpr int kG = 4 * kH;   // 4096

// Scratch for x_gates = input @ W_ih^T + bias_ih + bias_hh : [T*B, 4H] fp32 = 512 MB
__device__ float g_xg[(size_t)kT * kB * kG];

__global__ void copy_kernel(const float* __restrict__ src, float* __restrict__ dst, int n) {
    int i = blockIdx.x * blockDim.x + threadIdx.x;
    if (i < n) dst[i] = src[i];
}

// C[m][n] = sum_k x[m][k] * wih[n][k] + bih[n] + bhh[n]
// M = T*B = 32768, N = 4H = 4096, K = I = 1024
// Tiles: 64x64x16, 256 threads, 4x4 per thread. Smem transposed [k][row] for LDS.128.
__global__ __launch_bounds__(256) void xgates_kernel(
    const float* __restrict__ x, const float* __restrict__ wih,
    const float* __restrict__ bih, const float* __restrict__ bhh)
{
    __shared__ __align__(16) float As[16][68];
    __shared__ __align__(16) float Bs[16][68];
    const int m0 = blockIdx.y * 64;
    const int n0 = blockIdx.x * 64;
    const int tid = threadIdx.x;
    const int tx = tid & 15;       // n-subtile
    const int ty = tid >> 4;       // m-subtile
    const int lr = tid >> 2;       // 0..63 load row
    const int lc = (tid & 3) << 2; // 0,4,8,12 load col (float4)

    float acc[4][4] = {};

    for (int k0 = 0; k0 < kI; k0 += 16) {
        float4 va = *(const float4*)(x   + (size_t)(m0 + lr) * kI + k0 + lc);
        float4 vb = *(const float4*)(wih + (size_t)(n0 + lr) * kI + k0 + lc);
        As[lc + 0][lr] = va.x; As[lc + 1][lr] = va.y; As[lc + 2][lr] = va.z; As[lc + 3][lr] = va.w;
        Bs[lc + 0][lr] = vb.x; Bs[lc + 1][lr] = vb.y; Bs[lc + 2][lr] = vb.z; Bs[lc + 3][lr] = vb.w;
        __syncthreads();
        #pragma unroll
        for (int kk = 0; kk < 16; kk++) {
            float4 a4 = *(const float4*)&As[kk][ty * 4];
            float4 b4 = *(const float4*)&Bs[kk][tx * 4];
            float av[4] = {a4.x, a4.y, a4.z, a4.w};
            float bv[4] = {b4.x, b4.y, b4.z, b4.w};
            #pragma unroll
            for (int i = 0; i < 4; i++)
                #pragma unroll
                for (int j = 0; j < 4; j++)
                    acc[i][j] += av[i] * bv[j];
        }
        __syncthreads();
    }

    #pragma unroll
    for (int i = 0; i < 4; i++) {
        const int m = m0 + ty * 4 + i;
        float* orow = g_xg + (size_t)m * kG;
        #pragma unroll
        for (int j = 0; j < 4; j++) {
            const int n = n0 + tx * 4 + j;
            orow[n] = acc[i][j] + bih[n] + bhh[n];
        }
    }
}

// One recurrent step, fused: gates GEMM (64 x 4H x H) + activations + c/h update.
// Grid: 128 blocks (each owns 8 hidden columns), 128 threads.
// Thread (bg, j): 4 batches (bg*4..+3) x 4 gates for hidden column j0+j.
__global__ __launch_bounds__(128) void step_kernel(
    int t, const float* __restrict__ h_in, const float* __restrict__ whh,
    float* __restrict__ out, float* __restrict__ cbuf)
{
    __shared__ __align__(16) float Hs[32][68]; // [kk][batch]
    __shared__ float Ws[32][33];               // [kk][r], r = gate*8 + j
    const int j0  = blockIdx.x * 8;
    const int tid = threadIdx.x;
    const int j   = tid & 7;
    const int b0  = (tid >> 3) * 4;   // batch base, 0..60

    float acc[4][4] = {};  // [batch_sub][gate]

    for (int k0 = 0; k0 < kH; k0 += 32) {
        // Hs: 64 rows x 32 k -> 512 float4 loads / 128 threads
        #pragma unroll
        for (int u = 0; u < 4; u++) {
            const int idx = tid + u * 128;      // 0..511
            const int r   = idx >> 3;           // batch 0..63
            const int c4  = (idx & 7) << 2;     // k offset
            float4 v = *(const float4*)(h_in + (size_t)r * kH + k0 + c4);
            Hs[c4 + 0][r] = v.x; Hs[c4 + 1][r] = v.y; Hs[c4 + 2][r] = v.z; Hs[c4 + 3][r] = v.w;
        }
        // Ws: 32 rows (4 gates x 8 cols) x 32 k -> 256 float4 loads
        #pragma unroll
        for (int u = 0; u < 2; u++) {
            const int idx  = tid + u * 128;     // 0..255
            const int r    = idx >> 3;          // 0..31
            const int c4   = (idx & 7) << 2;
            const int grow = (r >> 3) * kH + j0 + (r & 7);
            float4 v = *(const float4*)(whh + (size_t)grow * kH + k0 + c4);
            Ws[c4 + 0][r] = v.x; Ws[c4 + 1][r] = v.y; Ws[c4 + 2][r] = v.z; Ws[c4 + 3][r] = v.w;
        }
        __syncthreads();
        #pragma unroll 8
        for (int kk = 0; kk < 32; kk++) {
            float4 h4 = *(const float4*)&Hs[kk][b0];
            float hv[4] = {h4.x, h4.y, h4.z, h4.w};
            float wv[4];
            #pragma unroll
            for (int g = 0; g < 4; g++) wv[g] = Ws[kk][g * 8 + j];
            #pragma unroll
            for (int i = 0; i < 4; i++)
                #pragma unroll
                for (int g = 0; g < 4; g++)
                    acc[i][g] += hv[i] * wv[g];
        }
        __syncthreads();
    }

    const int jj = j0 + j;
    #pragma unroll
    for (int i = 0; i < 4; i++) {
        const int b = b0 + i;
        const float* xg = g_xg + ((size_t)t * kB + b) * kG;
        float gi = acc[i][0] + xg[jj];
        float gf = acc[i][1] + xg[kH + jj];
        float gg = acc[i][2] + xg[2 * kH + jj];
        float go = acc[i][3] + xg[3 * kH + jj];
        gi = 1.f / (1.f + expf(-gi));
        gf = 1.f / (1.f + expf(-gf));
        gg = tanhf(gg);
        go = 1.f / (1.f + expf(-go));
        const int ci = b * kH + jj;
        const float cy = gf * cbuf[ci] + gi * gg;
        cbuf[ci] = cy;
        out[((size_t)t * kB + b) * kH + jj] = go * tanhf(cy);
    }
}

extern "C" void kernel_launch(void* const* d_in, const int* in_sizes, int n_in,
                              void* d_out, int out_size) {
    const float* x   = (const float*)d_in[0];
    const float* h0  = (const float*)d_in[1];
    const float* c0  = (const float*)d_in[2];
    const float* wih = (const float*)d_in[3];
    const float* whh = (const float*)d_in[4];
    const float* bih = (const float*)d_in[5];
    const float* bhh = (const float*)d_in[6];
    float* out  = (float*)d_out;
    float* cbuf = out + (size_t)kT * kB * kH;   // cT slot doubles as running c state

    // init c state
    copy_kernel<<<(kB * kH + 255) / 256, 256>>>(c0, cbuf, kB * kH);

    // phase 1: all input projections in one big GEMM
    xgates_kernel<<<dim3(kG / 64, (kT * kB) / 64), 256>>>(x, wih, bih, bhh);

    // phase 2: sequential recurrence; out[t-1] is h_{t-1}
    for (int t = 0; t < kT; t++) {
        const float* h_in = (t == 0) ? h0 : (out + (size_t)(t - 1) * kB * kH);
        step_kernel<<<128, 128>>>(t, h_in, whh, out, cbuf);
    }
}

// round 2
// speedup vs baseline: 1.7315x; 1.7315x over previous
#include <cuda_runtime.h>
#include <math.h>

typedef unsigned long long ull;

static constexpr int kT = 512;
static constexpr int kB = 64;
static constexpr int kI = 1024;
static constexpr int kH = 1024;
static constexpr int kG = 4 * kH;   // 4096
static constexpr int NBLK = 128;
static constexpr int NTHR = 512;

// Scratch for x_gates = input @ W_ih^T + bias_ih + bias_hh : [T*B, 4H] fp32 = 512 MB
__device__ float g_xg[(size_t)kT * kB * kG];
// grid barrier state (reset by init_kernel every launch)
__device__ unsigned g_cnt;
__device__ unsigned g_rel;

// ---------- packed f32x2 helpers (Blackwell FFMA2 path) ----------
__device__ __forceinline__ void ffma2(ull &d, ull a, ull b) {
    asm("fma.rn.f32x2 %0, %1, %2, %0;" : "+l"(d) : "l"(a), "l"(b));
}
__device__ __forceinline__ ull add2(ull a, ull b) {
    ull r; asm("add.rn.f32x2 %0, %1, %2;" : "=l"(r) : "l"(a), "l"(b)); return r;
}
__device__ __forceinline__ ull dup2(float x) {
    unsigned u = __float_as_uint(x);
    ull r; asm("mov.b64 %0, {%1, %1};" : "=l"(r) : "r"(u)); return r;
}
__device__ __forceinline__ float2 unpk(ull v) {
    unsigned lo, hi;
    asm("mov.b64 {%0, %1}, %2;" : "=r"(lo), "=r"(hi) : "l"(v));
    return make_float2(__uint_as_float(lo), __uint_as_float(hi));
}

__device__ __forceinline__ float sigf(float x) { return 1.f / (1.f + __expf(-x)); }
__device__ __forceinline__ float tanh_fast(float x) {
    // safe for large |x|: expf(inf)->inf -> t->0 -> r->1
    float t = 2.f / (__expf(2.f * fabsf(x)) + 1.f);
    float r = 1.f - t;
    return x >= 0.f ? r : -r;
}

__global__ void init_kernel() { g_cnt = 0u; g_rel = 0u; }

// ============================================================================
// Phase 1: x_gates GEMM. C[m][n] = sum_k x[m][k]*wih[n][k] + bih[n] + bhh[n]
// M=32768, N=4096, K=1024. Tile 128x128, 256 threads, 8x8 per thread, FFMA2.
// ============================================================================
__global__ __launch_bounds__(256, 2) void xgates_kernel(
    const float* __restrict__ x, const float* __restrict__ wih,
    const float* __restrict__ bih, const float* __restrict__ bhh)
{
    __shared__ __align__(16) float As[16][128];
    __shared__ __align__(16) float Bs[16][128];
    const int tid = threadIdx.x;
    const int tx = tid & 15;
    const int ty = tid >> 4;
    const int m0 = blockIdx.y * 128;
    const int n0 = blockIdx.x * 128;
    const int lr = tid >> 1;          // 0..127
    const int lc = (tid & 1) * 8;     // 0 or 8

    ull acc[8][4];
    #pragma unroll
    for (int i = 0; i < 8; i++)
        #pragma unroll
        for (int q = 0; q < 4; q++) acc[i][q] = 0ULL;

    const float* aptr = x   + (size_t)(m0 + lr) * kI + lc;
    const float* bptr = wih + (size_t)(n0 + lr) * kI + lc;

    // register-staged double buffering
    float4 a0r = *(const float4*)(aptr);
    float4 a1r = *(const float4*)(aptr + 4);
    float4 b0r = *(const float4*)(bptr);
    float4 b1r = *(const float4*)(bptr + 4);

    for (int k0 = 0; k0 < kI; k0 += 16) {
        As[lc + 0][lr] = a0r.x; As[lc + 1][lr] = a0r.y; As[lc + 2][lr] = a0r.z; As[lc + 3][lr] = a0r.w;
        As[lc + 4][lr] = a1r.x; As[lc + 5][lr] = a1r.y; As[lc + 6][lr] = a1r.z; As[lc + 7][lr] = a1r.w;
        Bs[lc + 0][lr] = b0r.x; Bs[lc + 1][lr] = b0r.y; Bs[lc + 2][lr] = b0r.z; Bs[lc + 3][lr] = b0r.w;
        Bs[lc + 4][lr] = b1r.x; Bs[lc + 5][lr] = b1r.y; Bs[lc + 6][lr] = b1r.z; Bs[lc + 7][lr] = b1r.w;
        __syncthreads();
        if (k0 + 16 < kI) {   // prefetch next chunk while computing
            a0r = *(const float4*)(aptr + k0 + 16);
            a1r = *(const float4*)(aptr + k0 + 20);
            b0r = *(const float4*)(bptr + k0 + 16);
            b1r = *(const float4*)(bptr + k0 + 20);
        }
        #pragma unroll 8
        for (int kk = 0; kk < 16; kk++) {
            float4 a0 = *(const float4*)&As[kk][ty * 8];
            float4 a1 = *(const float4*)&As[kk][ty * 8 + 4];
            ulonglong2 bp01 = *(const ulonglong2*)&Bs[kk][tx * 8];
            ulonglong2 bp23 = *(const ulonglong2*)&Bs[kk][tx * 8 + 4];
            float av[8] = {a0.x, a0.y, a0.z, a0.w, a1.x, a1.y, a1.z, a1.w};
            #pragma unroll
            for (int i = 0; i < 8; i++) {
                ull ad = dup2(av[i]);
                ffma2(acc[i][0], ad, bp01.x);
                ffma2(acc[i][1], ad, bp01.y);
                ffma2(acc[i][2], ad, bp23.x);
                ffma2(acc[i][3], ad, bp23.y);
            }
        }
        __syncthreads();
    }

    const int nbase = n0 + tx * 8;
    float bias[8];
    #pragma unroll
    for (int q = 0; q < 8; q++) bias[q] = bih[nbase + q] + bhh[nbase + q];
    #pragma unroll
    for (int i = 0; i < 8; i++) {
        int m = m0 + ty * 8 + i;
        float* orow = g_xg + (size_t)m * kG + nbase;
        float2 p0 = unpk(acc[i][0]), p1 = unpk(acc[i][1]);
        float2 p2 = unpk(acc[i][2]), p3 = unpk(acc[i][3]);
        float4 o0 = make_float4(p0.x + bias[0], p0.y + bias[1], p1.x + bias[2], p1.y + bias[3]);
        float4 o1 = make_float4(p2.x + bias[4], p2.y + bias[5], p3.x + bias[6], p3.y + bias[7]);
        *(float4*)(orow)     = o0;
        *(float4*)(orow + 4) = o1;
    }
}

// ============================================================================
// Phase 2: persistent recurrence. 128 blocks x 512 threads, all co-resident.
// Block owns 8 hidden cols (all 4 gates, all 64 batches). W_hh slice + c state
// live in smem for the whole kernel. 4-way K split + smem reduce. FFMA2 inner.
// ============================================================================
static constexpr int HS_STRIDE = 66;                      // pad: conflict/alignment
static constexpr int OFF_W  = 0;                          // 32768 floats (128 KB)
static constexpr int OFF_HS = 32768;                      // 4*32*66 = 8448
static constexpr int OFF_R  = OFF_HS + 4 * 32 * HS_STRIDE; // 41216, 6144 floats
static constexpr int OFF_C  = OFF_R + 3 * 128 * 16;       // 47360, 512 floats
static constexpr int SMEM_FLOATS = OFF_C + 512;           // 47872 -> 187 KB

__global__ __launch_bounds__(NTHR, 1) void lstm_persistent(
    const float* __restrict__ h0, const float* __restrict__ c0,
    const float* __restrict__ whh, float* __restrict__ out)
{
    extern __shared__ float sm[];
    float* Wp   = sm + OFF_W;    // [k][j][g] : k*32 + j*4 + g
    float* Hs   = sm + OFF_HS;   // [ks][kk][b] stride 66
    float* Rbuf = sm + OFF_R;    // [ks-1][lane127][16]
    float* cb   = sm + OFF_C;    // [b][j] : b*8 + j

    const int tid = threadIdx.x;
    const int j0  = blockIdx.x * 8;
    const int ks  = tid >> 7;          // K-split 0..3
    const int L   = tid & 127;
    const int j   = L & 7;
    const int b0  = (L >> 3) << 2;     // batch base 0..60
    const int jj  = j0 + j;

    // Load W_hh slice into smem once: Wp[k*32 + j*4 + g] = whh[g*1024 + j0+j][k]
    for (int idx = tid; idx < 32768; idx += NTHR) {
        int k = idx >> 5, r = idx & 31;
        int wj = r >> 2, g = r & 3;
        Wp[idx] = whh[(size_t)(g * kH + j0 + wj) * kH + k];
    }
    // c state into smem
    for (int idx = tid; idx < 512; idx += NTHR)
        cb[idx] = c0[(size_t)(idx >> 3) * kH + j0 + (idx & 7)];
    __syncthreads();

    for (int t = 0; t < kT; t++) {
        const float* hsrc = (t == 0) ? h0 : out + (size_t)(t - 1) * (kB * kH);

        // prefetch x_gates contributions (consumed after the GEMM)
        float xgv[16];
        if (ks == 0) {
            const float* xgb = g_xg + ((size_t)t * kB + b0) * kG + jj;
            #pragma unroll
            for (int i = 0; i < 4; i++)
                #pragma unroll
                for (int g = 0; g < 4; g++)
                    xgv[i * 4 + g] = xgb[(size_t)i * kG + g * kH];
        }

        ull acc[2][4];
        #pragma unroll
        for (int p = 0; p < 2; p++)
            #pragma unroll
            for (int g = 0; g < 4; g++) acc[p][g] = 0ULL;

        for (int k0 = 0; k0 < 256; k0 += 32) {
            // stage h chunk for all 4 K-splits: [ks][32 k][64 b], transposed
            #pragma unroll
            for (int u = 0; u < 4; u++) {
                int idx = tid + u * NTHR;          // 0..2047
                int ksl = idx >> 9;
                int rem = idx & 511;
                int b   = rem >> 3;
                int kq  = (rem & 7) << 2;
                float4 v = *(const float4*)(hsrc + (size_t)b * kH + ksl * 256 + k0 + kq);
                float* hp = Hs + ksl * (32 * HS_STRIDE) + kq * HS_STRIDE + b;
                hp[0]             = v.x;
                hp[HS_STRIDE]     = v.y;
                hp[2 * HS_STRIDE] = v.z;
                hp[3 * HS_STRIDE] = v.w;
            }
            __syncthreads();
            const float* wbase = Wp + ((ks << 8) + k0) * 32 + (j << 2);
            const float* hbase = Hs + ks * (32 * HS_STRIDE) + b0;
            #pragma unroll 16
            for (int kk = 0; kk < 32; kk++) {
                float4 w = *(const float4*)(wbase + kk * 32);
                ull h01 = *(const ull*)(hbase + kk * HS_STRIDE);
                ull h23 = *(const ull*)(hbase + kk * HS_STRIDE + 2);
                ull w0 = dup2(w.x), w1 = dup2(w.y), w2 = dup2(w.z), w3 = dup2(w.w);
                ffma2(acc[0][0], h01, w0); ffma2(acc[1][0], h23, w0);
                ffma2(acc[0][1], h01, w1); ffma2(acc[1][1], h23, w1);
                ffma2(acc[0][2], h01, w2); ffma2(acc[1][2], h23, w2);
                ffma2(acc[0][3], h01, w3); ffma2(acc[1][3], h23, w3);
            }
            __syncthreads();
        }

        // cross-K-split reduction through smem
        if (ks != 0) {
            ull* rp = (ull*)(Rbuf + ((ks - 1) * 128 + L) * 16);
            #pragma unroll
            for (int p = 0; p < 2; p++)
                #pragma unroll
                for (int g = 0; g < 4; g++) rp[p * 4 + g] = acc[p][g];
        }
        __syncthreads();

        if (ks == 0) {
            #pragma unroll
            for (int s = 0; s < 3; s++) {
                const ull* rp = (const ull*)(Rbuf + (s * 128 + L) * 16);
                #pragma unroll
                for (int p = 0; p < 2; p++)
                    #pragma unroll
                    for (int g = 0; g < 4; g++) acc[p][g] = add2(acc[p][g], rp[p * 4 + g]);
            }
            // fused LSTM cell update
            float* orow = out + (size_t)t * (kB * kH);
            #pragma unroll
            for (int p = 0; p < 2; p++) {
                float2 vi = unpk(acc[p][0]);
                float2 vf = unpk(acc[p][1]);
                float2 vg = unpk(acc[p][2]);
                float2 vo = unpk(acc[p][3]);
                #pragma unroll
                for (int hh = 0; hh < 2; hh++) {
                    int i = p * 2 + hh;
                    int b = b0 + i;
                    float gi = (hh ? vi.y : vi.x) + xgv[i * 4 + 0];
                    float gf = (hh ? vf.y : vf.x) + xgv[i * 4 + 1];
                    float gg = (hh ? vg.y : vg.x) + xgv[i * 4 + 2];
                    float go = (hh ? vo.y : vo.x) + xgv[i * 4 + 3];
                    gi = sigf(gi); gf = sigf(gf); gg = tanh_fast(gg); go = sigf(go);
                    float c  = cb[b * 8 + j];
                    float cy = gf * c + gi * gg;
                    cb[b * 8 + j] = cy;
                    orow[(size_t)b * kH + jj] = go * tanh_fast(cy);
                }
            }
        }

        // grid barrier between steps (release/acquire via L2)
        if (t < kT - 1) {
            __threadfence();
            __syncthreads();
            if (tid == 0) {
                unsigned arr = atomicAdd(&g_cnt, 1u) + 1u;
                unsigned tgt = (unsigned)(t + 1) * NBLK;
                if (arr == tgt) {
                    __threadfence();
                    atomicExch(&g_rel, (unsigned)(t + 1));
                } else {
                    while (*((volatile unsigned*)&g_rel) < (unsigned)(t + 1)) { }
                    __threadfence();
                }
            }
            __syncthreads();
        }
    }

    // final cell state
    if (ks == 0) {
        float* cT = out + (size_t)kT * kB * kH;
        #pragma unroll
        for (int i = 0; i < 4; i++) {
            int b = b0 + i;
            cT[(size_t)b * kH + jj] = cb[b * 8 + j];
        }
    }
}

extern "C" void kernel_launch(void* const* d_in, const int* in_sizes, int n_in,
                              void* d_out, int out_size) {
    const float* x   = (const float*)d_in[0];
    const float* h0  = (const float*)d_in[1];
    const float* c0  = (const float*)d_in[2];
    const float* wih = (const float*)d_in[3];
    const float* whh = (const float*)d_in[4];
    const float* bih = (const float*)d_in[5];
    const float* bhh = (const float*)d_in[6];
    float* out = (float*)d_out;

    cudaFuncSetAttribute(lstm_persistent,
                         cudaFuncAttributeMaxDynamicSharedMemorySize,
                         SMEM_FLOATS * (int)sizeof(float));

    init_kernel<<<1, 1>>>();
    xgates_kernel<<<dim3(kG / 128, (kT * kB) / 128), 256>>>(x, wih, bih, bhh);
    lstm_persistent<<<NBLK, NTHR, SMEM_FLOATS * sizeof(float)>>>(h0, c0, whh, out);
}

// round 4
// speedup vs baseline: 3.9454x; 2.2786x over previous
#include <cuda_runtime.h>
#include <cuda_bf16.h>
#include <math.h>
#include <stdint.h>

typedef uint32_t u32;
typedef uint64_t u64;

static constexpr int kT = 512;
static constexpr int kB = 64;
static constexpr int kH = 1024;
static constexpr int kG = 4096;
static constexpr int RBLK = 128;   // recurrence blocks (64 j-slices x 2 batch halves)

// ---------------- global scratch ----------------
__device__ float         g_xg[(size_t)kT * kB * kG];     // x-gates fp32 (incl. biases)
__device__ __nv_bfloat16 g_xh[(size_t)kT * kB * kH];     // x hi
__device__ __nv_bfloat16 g_xl[(size_t)kT * kB * kH];     // x lo
__device__ __nv_bfloat16 g_wihh[(size_t)kG * kH];
__device__ __nv_bfloat16 g_wihl[(size_t)kG * kH];
__device__ __nv_bfloat16 g_wph[(size_t)kG * kH];         // W_hh hi packed [jblk][l][k]
__device__ __nv_bfloat16 g_wpl[(size_t)kG * kH];         // W_hh lo packed [jblk][ch][l][kk]
__device__ __nv_bfloat16 g_hh[2][kB * kH];               // h hi double buffered [b][k]
__device__ __nv_bfloat16 g_hl[2][kB * kH];               // h lo
__device__ unsigned g_cnt, g_rel;

// ---------------- PTX helpers ----------------
__device__ __forceinline__ u32 smem_u32(const void* p) {
    u32 a;
    asm("{ .reg .u64 t; cvta.to.shared.u64 t, %1; cvt.u32.u64 %0, t; }" : "=r"(a) : "l"(p));
    return a;
}
__device__ __forceinline__ void cp16(u32 dst, const void* src) {
    asm volatile("cp.async.cg.shared.global [%0], [%1], 16;" :: "r"(dst), "l"(src) : "memory");
}
__device__ __forceinline__ void cp_commit() { asm volatile("cp.async.commit_group;" ::: "memory"); }
__device__ __forceinline__ void cp_wait0()  { asm volatile("cp.async.wait_group 0;" ::: "memory"); }
__device__ __forceinline__ void cp_wait1()  { asm volatile("cp.async.wait_group 1;" ::: "memory"); }

__device__ __forceinline__ void ldm4(u32 a, u32* r) {
    asm volatile("ldmatrix.sync.aligned.m8n8.x4.shared.b16 {%0,%1,%2,%3}, [%4];"
                 : "=r"(r[0]), "=r"(r[1]), "=r"(r[2]), "=r"(r[3]) : "r"(a));
}
__device__ __forceinline__ void ldm2(u32 a, u32* r) {
    asm volatile("ldmatrix.sync.aligned.m8n8.x2.shared.b16 {%0,%1}, [%2];"
                 : "=r"(r[0]), "=r"(r[1]) : "r"(a));
}
__device__ __forceinline__ void mma_bf16(float* c, const u32* a, u32 b0, u32 b1) {
    asm volatile("mma.sync.aligned.m16n8k16.row.col.f32.bf16.bf16.f32 "
                 "{%0,%1,%2,%3}, {%4,%5,%6,%7}, {%8,%9}, {%0,%1,%2,%3};"
                 : "+f"(c[0]), "+f"(c[1]), "+f"(c[2]), "+f"(c[3])
                 : "r"(a[0]), "r"(a[1]), "r"(a[2]), "r"(a[3]), "r"(b0), "r"(b1));
}
// swizzled 16B-unit offset: row r, unit u, row stride (bytes, multiple of 128)
__device__ __forceinline__ u32 swof(int r, int u, int stride) {
    return (u32)(r * stride + ((u >> 3) << 7) + (((u ^ r) & 7) << 4));
}

__device__ __forceinline__ float sigf(float x) { return 1.f / (1.f + __expf(-x)); }
__device__ __forceinline__ float tanh_fast(float x) {
    float t = 2.f / (__expf(2.f * fabsf(x)) + 1.f);
    float r = 1.f - t;
    return x >= 0.f ? r : -r;
}

// ---------------- prep kernels ----------------
__global__ void init_kernel() { g_cnt = 0u; g_rel = 0u; }

__global__ void split_x(const float* __restrict__ s, int n) {
    for (int i = blockIdx.x * blockDim.x + threadIdx.x; i < n; i += gridDim.x * blockDim.x) {
        float v = s[i];
        __nv_bfloat16 hi = __float2bfloat16_rn(v);
        g_xh[i] = hi;
        g_xl[i] = __float2bfloat16_rn(v - __bfloat162float(hi));
    }
}
__global__ void split_w(const float* __restrict__ s, int n) {
    for (int i = blockIdx.x * blockDim.x + threadIdx.x; i < n; i += gridDim.x * blockDim.x) {
        float v = s[i];
        __nv_bfloat16 hi = __float2bfloat16_rn(v);
        g_wihh[i] = hi;
        g_wihl[i] = __float2bfloat16_rn(v - __bfloat162float(hi));
    }
}
__global__ void split_h0(const float* __restrict__ s, int n) {
    for (int i = blockIdx.x * blockDim.x + threadIdx.x; i < n; i += gridDim.x * blockDim.x) {
        float v = s[i];
        __nv_bfloat16 hi = __float2bfloat16_rn(v);
        g_hh[0][i] = hi;
        g_hl[0][i] = __float2bfloat16_rn(v - __bfloat162float(hi));
    }
}
// g_wph[(jblk*64 + l)*1024 + k], l = g*16 + jl, src row g*1024 + jblk*16 + jl
// g_wpl[((jblk*8 + ch)*64 + l)*128 + kk], ch = k>>7, kk = k&127
__global__ void pack_whh(const float* __restrict__ whh) {
    const int n = kG * kH;
    for (int i = blockIdx.x * blockDim.x + threadIdx.x; i < n; i += gridDim.x * blockDim.x) {
        int k    = i & 1023;
        int l    = (i >> 10) & 63;
        int jblk = i >> 16;
        int g = l >> 4, jl = l & 15;
        float v = whh[(size_t)(g * kH + jblk * 16 + jl) * kH + k];
        __nv_bfloat16 hi = __float2bfloat16_rn(v);
        g_wph[i] = hi;
        size_t li = ((size_t)(jblk * 8 + (k >> 7)) * 64 + l) * 128 + (k & 127);
        g_wpl[li] = __float2bfloat16_rn(v - __bfloat162float(hi));
    }
}

// ============================================================================
// Phase 1: x-gates GEMM (HMMA). C[32768, 4096] = x @ Wih^T + biases.
// 128x128 tile, 256 thr (8 warps: mg 0-3, ng 0-1; warp tile 32x64).
// K chunks of 64, double buffered. Split-bf16: 3 mma per tile pair.
// ============================================================================
static constexpr int XAH = 0;            // per-buffer layout (bytes)
static constexpr int XAL = 16384;
static constexpr int XBH = 32768;
static constexpr int XBL = 49152;
static constexpr int XBUFSZ = 65536;
static constexpr int XBIAS  = 2 * XBUFSZ;        // 131072
static constexpr int XG_SMEM = XBIAS + 512;

__global__ __launch_bounds__(256, 1) void xgates_tc(
    const float* __restrict__ bih, const float* __restrict__ bhh)
{
    extern __shared__ char sm[];
    const u32 sb  = smem_u32(sm);
    const int tid = threadIdx.x;
    const int wid = tid >> 5;
    const int ln  = tid & 31;
    const int mg  = wid & 3;
    const int ng  = wid >> 2;
    const int n0  = blockIdx.x * 128;
    const int m0  = blockIdx.y * 128;
    float* bias_s = (float*)(sm + XBIAS);

    if (tid < 128) bias_s[tid] = bih[n0 + tid] + bhh[n0 + tid];

    auto stage = [&](int ch, u32 buf) {
        #pragma unroll
        for (int rep = 0; rep < 4; rep++) {
            int idx = tid + rep * 256;      // 0..1023 : 128 rows x 8 units
            int r = idx >> 3, u = idx & 7;
            u32 sw = swof(r, u, 128);
            size_t go = (size_t)(m0 + r) * kH + ch * 64 + u * 8;
            size_t gn = (size_t)(n0 + r) * kH + ch * 64 + u * 8;
            cp16(buf + XAH + sw, (const char*)g_xh   + go * 2);
            cp16(buf + XAL + sw, (const char*)g_xl   + go * 2);
            cp16(buf + XBH + sw, (const char*)g_wihh + gn * 2);
            cp16(buf + XBL + sw, (const char*)g_wihl + gn * 2);
        }
        cp_commit();
    };

    float c[2][8][4];
    #pragma unroll
    for (int i = 0; i < 2; i++)
        #pragma unroll
        for (int j = 0; j < 8; j++)
            #pragma unroll
            for (int q = 0; q < 4; q++) c[i][j][q] = 0.f;

    stage(0, sb);
    for (int ch = 0; ch < 16; ch++) {
        const u32 buf = sb + (ch & 1) * XBUFSZ;
        if (ch < 15) { stage(ch + 1, sb + ((ch + 1) & 1) * XBUFSZ); cp_wait1(); }
        else cp_wait0();
        __syncthreads();
        #pragma unroll
        for (int k2 = 0; k2 < 4; k2++) {
            const int ua = k2 * 2 + (ln >> 4);
            u32 ah[2][4], al[2][4];
            #pragma unroll
            for (int mt = 0; mt < 2; mt++) {
                int r = mg * 32 + mt * 16 + (ln & 15);
                ldm4(buf + XAH + swof(r, ua, 128), ah[mt]);
                ldm4(buf + XAL + swof(r, ua, 128), al[mt]);
            }
            u32 bh[4][4], bl[4][4];
            #pragma unroll
            for (int p = 0; p < 4; p++) {
                int r = ng * 64 + p * 16 + (ln & 7) + ((ln & 16) >> 1);
                int u = k2 * 2 + ((ln >> 3) & 1);
                ldm4(buf + XBH + swof(r, u, 128), bh[p]);
                ldm4(buf + XBL + swof(r, u, 128), bl[p]);
            }
            #pragma unroll
            for (int mt = 0; mt < 2; mt++)
                #pragma unroll
                for (int nt = 0; nt < 8; nt++) {
                    const int p = nt >> 1, o = (nt & 1) * 2;
                    mma_bf16(c[mt][nt], ah[mt], bh[p][o], bh[p][o + 1]);
                    mma_bf16(c[mt][nt], ah[mt], bl[p][o], bl[p][o + 1]);
                    mma_bf16(c[mt][nt], al[mt], bh[p][o], bh[p][o + 1]);
                }
        }
        __syncthreads();
    }

    // epilogue: add bias, store fp32
    #pragma unroll
    for (int mt = 0; mt < 2; mt++) {
        const int row = m0 + mg * 32 + mt * 16 + (ln >> 2);
        #pragma unroll
        for (int nt = 0; nt < 8; nt++) {
            const int col = ng * 64 + nt * 8 + (ln & 3) * 2;
            float b0 = bias_s[col], b1 = bias_s[col + 1];
            float2 v0 = make_float2(c[mt][nt][0] + b0, c[mt][nt][1] + b1);
            float2 v1 = make_float2(c[mt][nt][2] + b0, c[mt][nt][3] + b1);
            *(float2*)(g_xg + (size_t)row * kG + n0 + col)       = v0;
            *(float2*)(g_xg + (size_t)(row + 8) * kG + n0 + col) = v1;
        }
    }
}

// ============================================================================
// Phase 2: persistent recurrence (HMMA). 128 blocks x 512 threads.
// Block (jblk, bh): C[64 gate-rows, 32 batch] = Wslice @ h^T, K=1024, split-bf16.
// W_hi resident in smem; W_lo + h hi/lo streamed per step (8 chunks of K=128).
// 16 warps: (mg 0-1) x (ng 0-3) x (ks 0-1); warp tile 32x8, K half = 512.
// ============================================================================
static constexpr int RWHI  = 0;                    // 64 x 2048 B = 131072
static constexpr int RBUF0 = 131072;               // WLO 16K | HHI 8K | HLO 8K
static constexpr int RWLO  = 0;
static constexpr int RHHI  = 16384;
static constexpr int RHLO  = 24576;
static constexpr int RBUFSZ = 32768;
static constexpr int RRED  = RBUF0 + 2 * RBUFSZ;   // 196608: 2*64*32 f32 = 16384
static constexpr int RHBUF = RRED + 16384;         // 212992: 16*33 f32
static constexpr int RCSM  = RHBUF + 16 * 33 * 4 + 16; // 215136ish
static constexpr int RC_SMEM = RCSM + 16 * 33 * 4 + 16;

__global__ __launch_bounds__(512, 1) void lstm_tc(
    const float* __restrict__ c0, float* __restrict__ out)
{
    extern __shared__ char sm[];
    const u32 sb  = smem_u32(sm);
    const int tid = threadIdx.x;
    const int wid = tid >> 5;
    const int ln  = tid & 31;
    const int jblk = blockIdx.x & 63;
    const int bhf  = blockIdx.x >> 6;
    const int j0   = jblk * 16;
    const int B0   = bhf * 32;
    const int mg = wid & 1, ng = (wid >> 1) & 3, ks = wid >> 3;
    float* red  = (float*)(sm + RRED);
    float* hbuf = (float*)(sm + RHBUF);
    float* csm  = (float*)(sm + RCSM);

    // preload W_hi (64 x 1024 bf16) into swizzled smem
    #pragma unroll
    for (int rep = 0; rep < 16; rep++) {
        int idx = tid + rep * 512;           // 0..8191 : 64 rows x 128 units
        int r = idx >> 7, u = idx & 127;
        cp16(sb + RWHI + swof(r, u, 2048),
             (const char*)g_wph + ((size_t)(jblk * 64 + r) * kH + u * 8) * 2);
    }
    cp_commit();

    // c state: csm[jl*33 + b]
    {
        int jl = tid >> 5, b = tid & 31;
        csm[jl * 33 + b] = c0[(size_t)(B0 + b) * kH + j0 + jl];
    }

    auto stage = [&](int ch, u32 buf, const __nv_bfloat16* hh, const __nv_bfloat16* hl) {
        #pragma unroll
        for (int rep = 0; rep < 2; rep++) {
            int idx = tid + rep * 512;       // 0..1023 : 64 rows x 16 units
            int r = idx >> 4, u = idx & 15;
            cp16(buf + RWLO + swof(r, u, 256),
                 (const char*)g_wpl + ((size_t)((jblk * 8 + ch) * 64 + r) * 128 + u * 8) * 2);
        }
        {
            int r = tid >> 4, u = tid & 15;  // 32 rows x 16 units
            size_t go = ((size_t)(B0 + r) * kH + ch * 128 + u * 8) * 2;
            cp16(buf + RHHI + swof(r, u, 256), (const char*)hh + go);
            cp16(buf + RHLO + swof(r, u, 256), (const char*)hl + go);
        }
        cp_commit();
    };

    cp_wait0();
    __syncthreads();

    for (int t = 0; t < kT; t++) {
        const __nv_bfloat16* hh = g_hh[t & 1];
        const __nv_bfloat16* hl = g_hl[t & 1];

        // x-gates prefetch for this thread's cell (jl = tid>>5, b = tid&31)
        const int cjl = tid >> 5, cb = tid & 31;
        float xgv[4];
        {
            const float* xp = g_xg + ((size_t)t * kB + B0 + cb) * kG + j0 + cjl;
            #pragma unroll
            for (int g = 0; g < 4; g++) xgv[g] = xp[g * kH];
        }

        float c0f[4] = {0.f, 0.f, 0.f, 0.f};
        float c1f[4] = {0.f, 0.f, 0.f, 0.f};

        stage(0, sb + RBUF0, hh, hl);
        for (int ch = 0; ch < 8; ch++) {
            const u32 buf = sb + RBUF0 + (ch & 1) * RBUFSZ;
            if (ch < 7) { stage(ch + 1, sb + RBUF0 + ((ch + 1) & 1) * RBUFSZ, hh, hl); cp_wait1(); }
            else cp_wait0();
            __syncthreads();
            #pragma unroll
            for (int k2 = 0; k2 < 4; k2++) {
                const int uhi = ch * 16 + ks * 8 + k2 * 2 + (ln >> 4);
                const int ulo = ks * 8 + k2 * 2 + (ln >> 4);
                const int ub  = ks * 8 + k2 * 2 + ((ln >> 3) & 1);
                u32 ah0[4], ah1[4], al0[4], al1[4], bhr[2], blr[2];
                {
                    int r0 = mg * 32 + (ln & 15);
                    int r1 = r0 + 16;
                    ldm4(sb + RWHI + swof(r0, uhi, 2048), ah0);
                    ldm4(sb + RWHI + swof(r1, uhi, 2048), ah1);
                    ldm4(buf + RWLO + swof(r0, ulo, 256), al0);
                    ldm4(buf + RWLO + swof(r1, ulo, 256), al1);
                    int rb = ng * 8 + (ln & 7);
                    ldm2(buf + RHHI + swof(rb, ub, 256), bhr);
                    ldm2(buf + RHLO + swof(rb, ub, 256), blr);
                }
                mma_bf16(c0f, ah0, bhr[0], bhr[1]);
                mma_bf16(c1f, ah1, bhr[0], bhr[1]);
                mma_bf16(c0f, ah0, blr[0], blr[1]);
                mma_bf16(c1f, ah1, blr[0], blr[1]);
                mma_bf16(c0f, al0, bhr[0], bhr[1]);
                mma_bf16(c1f, al1, bhr[0], bhr[1]);
            }
            __syncthreads();
        }

        // write C frags to red[ks][row][col]
        {
            const int col = ng * 8 + (ln & 3) * 2;
            const int r0  = mg * 32 + (ln >> 2);
            float* rp = red + (size_t)ks * 2048;
            *(float2*)(rp + (r0)      * 32 + col) = make_float2(c0f[0], c0f[1]);
            *(float2*)(rp + (r0 + 8)  * 32 + col) = make_float2(c0f[2], c0f[3]);
            *(float2*)(rp + (r0 + 16) * 32 + col) = make_float2(c1f[0], c1f[1]);
            *(float2*)(rp + (r0 + 24) * 32 + col) = make_float2(c1f[2], c1f[3]);
        }
        __syncthreads();

        // fused cell update: thread -> cell (cjl, cb)
        {
            float gv[4];
            #pragma unroll
            for (int g = 0; g < 4; g++) {
                int row = g * 16 + cjl;
                gv[g] = red[row * 32 + cb] + red[2048 + row * 32 + cb] + xgv[g];
            }
            float gi = sigf(gv[0]);
            float gf = sigf(gv[1]);
            float gg = tanh_fast(gv[2]);
            float go = sigf(gv[3]);
            float cprev = csm[cjl * 33 + cb];
            float cy = gf * cprev + gi * gg;
            csm[cjl * 33 + cb] = cy;
            hbuf[cjl * 33 + cb] = go * tanh_fast(cy);
        }
        __syncthreads();

        // coalesced outputs: thread tt -> (b2 = tt>>4, jc = tt&15)
        {
            const int b2 = tid >> 4, jc = tid & 15;
            float hv = hbuf[jc * 33 + b2];
            out[((size_t)t * kB + B0 + b2) * kH + j0 + jc] = hv;
            __nv_bfloat16 hi = __float2bfloat16_rn(hv);
            const int wb = (t & 1) ^ 1;
            size_t off = (size_t)(B0 + b2) * kH + j0 + jc;
            g_hh[wb][off] = hi;
            g_hl[wb][off] = __float2bfloat16_rn(hv - __bfloat162float(hi));
        }

        // grid barrier between steps
        if (t < kT - 1) {
            __threadfence();
            __syncthreads();
            if (tid == 0) {
                unsigned a = atomicAdd(&g_cnt, 1u) + 1u;
                if (a == (unsigned)(t + 1) * RBLK) {
                    __threadfence();
                    atomicExch(&g_rel, (unsigned)(t + 1));
                } else {
                    while (*((volatile unsigned*)&g_rel) < (unsigned)(t + 1)) { }
                }
            }
            __syncthreads();
        }
    }

    // final cell state (coalesced)
    {
        const int b2 = tid >> 4, jc = tid & 15;
        float* cT = out + (size_t)kT * kB * kH;
        cT[(size_t)(B0 + b2) * kH + j0 + jc] = csm[jc * 33 + b2];
    }
}

// ============================================================================
extern "C" void kernel_launch(void* const* d_in, const int* in_sizes, int n_in,
                              void* d_out, int out_size) {
    const float* x   = (const float*)d_in[0];
    const float* h0  = (const float*)d_in[1];
    const float* c0  = (const float*)d_in[2];
    const float* wih = (const float*)d_in[3];
    const float* whh = (const float*)d_in[4];
    const float* bih = (const float*)d_in[5];
    const float* bhh = (const float*)d_in[6];
    float* out = (float*)d_out;

    static bool attr_set = false;
    if (!attr_set) {
        cudaFuncSetAttribute(xgates_tc, cudaFuncAttributeMaxDynamicSharedMemorySize, XG_SMEM);
        cudaFuncSetAttribute(lstm_tc,   cudaFuncAttributeMaxDynamicSharedMemorySize, RC_SMEM);
        attr_set = true;
    }

    init_kernel<<<1, 1>>>();
    split_x<<<4096, 256>>>(x, kT * kB * kH);
    split_w<<<1024, 256>>>(wih, kG * kH);
    split_h0<<<64, 256>>>(h0, kB * kH);
    pack_whh<<<1024, 256>>>(whh);
    xgates_tc<<<dim3(kG / 128, (kT * kB) / 128), 256, XG_SMEM>>>(bih, bhh);
    lstm_tc<<<RBLK, 512, RC_SMEM>>>(c0, out);
}

// round 6
// speedup vs baseline: 6.0625x; 1.5366x over previous
#include <cuda_runtime.h>
#include <cuda_fp16.h>
#include <math.h>
#include <stdint.h>

typedef uint32_t u32;

static constexpr int kT = 512;
static constexpr int kB = 64;
static constexpr int kH = 1024;
static constexpr int kG = 4096;
static constexpr int RBLK = 128;

// ---------------- global scratch ----------------
__device__ float  g_xg[(size_t)kT * kB * kG];      // x-gates fp32 (incl. biases)
__device__ __half g_x16[(size_t)kT * kB * kH];     // x fp16
__device__ __half g_wih_h[(size_t)kG * kH];        // W_ih hi
__device__ __half g_wih_l[(size_t)kG * kH];        // W_ih lo
__device__ __half g_wp_h[(size_t)kG * kH];         // W_hh hi packed [jblk][row][k]
__device__ __half g_wp_l[(size_t)kG * kH];         // W_hh lo packed
__device__ __half g_h16[2][kB * kH];               // h fp16, double buffered [b][k]
__device__ unsigned g_cnt, g_rel;

// ---------------- PTX helpers ----------------
__device__ __forceinline__ u32 smem_u32(const void* p) {
    u32 a;
    asm("{ .reg .u64 t; cvta.to.shared.u64 t, %1; cvt.u32.u64 %0, t; }" : "=r"(a) : "l"(p));
    return a;
}
__device__ __forceinline__ void cp16(u32 dst, const void* src) {
    asm volatile("cp.async.cg.shared.global [%0], [%1], 16;" :: "r"(dst), "l"(src) : "memory");
}
__device__ __forceinline__ void cp_commit() { asm volatile("cp.async.commit_group;" ::: "memory"); }
__device__ __forceinline__ void cp_wait0()  { asm volatile("cp.async.wait_group 0;" ::: "memory"); }
__device__ __forceinline__ void cp_wait1()  { asm volatile("cp.async.wait_group 1;" ::: "memory"); }

__device__ __forceinline__ void ldm4(u32 a, u32* r) {
    asm volatile("ldmatrix.sync.aligned.m8n8.x4.shared.b16 {%0,%1,%2,%3}, [%4];"
                 : "=r"(r[0]), "=r"(r[1]), "=r"(r[2]), "=r"(r[3]) : "r"(a));
}
__device__ __forceinline__ void mma_fp16(float* c, const u32* a, u32 b0, u32 b1) {
    asm volatile("mma.sync.aligned.m16n8k16.row.col.f32.f16.f16.f32 "
                 "{%0,%1,%2,%3}, {%4,%5,%6,%7}, {%8,%9}, {%0,%1,%2,%3};"
                 : "+f"(c[0]), "+f"(c[1]), "+f"(c[2]), "+f"(c[3])
                 : "r"(a[0]), "r"(a[1]), "r"(a[2]), "r"(a[3]), "r"(b0), "r"(b1));
}
// swizzled byte offset: row r, 16B-unit u, row stride bytes (multiple of 128)
__device__ __forceinline__ u32 swof(int r, int u, int stride) {
    return (u32)(r * stride + ((u >> 3) << 7) + (((u ^ r) & 7) << 4));
}

__device__ __forceinline__ float sigf(float x) { return 1.f / (1.f + __expf(-x)); }
__device__ __forceinline__ float tanh_fast(float x) {
    float t = 2.f / (__expf(2.f * fabsf(x)) + 1.f);
    float r = 1.f - t;
    return x >= 0.f ? r : -r;
}

// ---------------- prep kernels ----------------
__global__ void init_kernel() { g_cnt = 0u; g_rel = 0u; }

__global__ void split_x16(const float* __restrict__ s, int n) {
    for (int i = blockIdx.x * blockDim.x + threadIdx.x; i < n; i += gridDim.x * blockDim.x)
        g_x16[i] = __float2half_rn(s[i]);
}
__global__ void split_wih(const float* __restrict__ s, int n) {
    for (int i = blockIdx.x * blockDim.x + threadIdx.x; i < n; i += gridDim.x * blockDim.x) {
        float v = s[i];
        __half hi = __float2half_rn(v);
        g_wih_h[i] = hi;
        g_wih_l[i] = __float2half_rn(v - __half2float(hi));
    }
}
__global__ void split_h0_16(const float* __restrict__ s, int n) {
    for (int i = blockIdx.x * blockDim.x + threadIdx.x; i < n; i += gridDim.x * blockDim.x)
        g_h16[0][i] = __float2half_rn(s[i]);
}
// g_wp_*[(jblk*32 + row)*1024 + k], row = g*8 + jl, src row = g*1024 + jblk*8 + jl
__global__ void pack_whh16(const float* __restrict__ whh) {
    const int n = kG * kH;
    for (int i = blockIdx.x * blockDim.x + threadIdx.x; i < n; i += gridDim.x * blockDim.x) {
        int k    = i & 1023;
        int row  = (i >> 10) & 31;
        int jblk = i >> 15;
        int g = row >> 3, jl = row & 7;
        float v = whh[(size_t)(g * kH + jblk * 8 + jl) * kH + k];
        __half hi = __float2half_rn(v);
        g_wp_h[i] = hi;
        g_wp_l[i] = __float2half_rn(v - __half2float(hi));
    }
}

// ============================================================================
// Phase 1: x-gates GEMM (fp16 HMMA, 2-product). C = x @ Wih^T + biases.
// 128x128 tile, 256 thr, warp tile 32x64. K chunks of 64, double buffered.
// ============================================================================
static constexpr int XA   = 0;            // x fp16 (16 KB)
static constexpr int XWH  = 16384;        // W hi (16 KB)
static constexpr int XWL  = 32768;        // W lo (16 KB)
static constexpr int XBUFSZ = 49152;
static constexpr int XBIAS  = 2 * XBUFSZ;
static constexpr int XG_SMEM = XBIAS + 512;

__global__ __launch_bounds__(256, 2) void xgates_tc(
    const float* __restrict__ bih, const float* __restrict__ bhh)
{
    extern __shared__ char sm[];
    const u32 sb  = smem_u32(sm);
    const int tid = threadIdx.x;
    const int wid = tid >> 5;
    const int ln  = tid & 31;
    const int mg  = wid & 3;
    const int ng  = wid >> 2;
    const int n0  = blockIdx.x * 128;
    const int m0  = blockIdx.y * 128;
    float* bias_s = (float*)(sm + XBIAS);

    if (tid < 128) bias_s[tid] = bih[n0 + tid] + bhh[n0 + tid];

    auto stage = [&](int ch, u32 buf) {
        #pragma unroll
        for (int rep = 0; rep < 4; rep++) {
            int idx = tid + rep * 256;     // 0..1023 : 128 rows x 8 units
            int r = idx >> 3, u = idx & 7;
            u32 sw = swof(r, u, 128);
            cp16(buf + XA  + sw, (const char*)g_x16   + ((size_t)(m0 + r) * kH + ch * 64 + u * 8) * 2);
            cp16(buf + XWH + sw, (const char*)g_wih_h + ((size_t)(n0 + r) * kH + ch * 64 + u * 8) * 2);
            cp16(buf + XWL + sw, (const char*)g_wih_l + ((size_t)(n0 + r) * kH + ch * 64 + u * 8) * 2);
        }
        cp_commit();
    };

    float c[2][8][4];
    #pragma unroll
    for (int i = 0; i < 2; i++)
        #pragma unroll
        for (int j = 0; j < 8; j++)
            #pragma unroll
            for (int q = 0; q < 4; q++) c[i][j][q] = 0.f;

    stage(0, sb);
    for (int ch = 0; ch < 16; ch++) {
        const u32 buf = sb + (ch & 1) * XBUFSZ;
        if (ch < 15) { stage(ch + 1, sb + ((ch + 1) & 1) * XBUFSZ); cp_wait1(); }
        else cp_wait0();
        __syncthreads();
        #pragma unroll
        for (int k2 = 0; k2 < 4; k2++) {
            u32 ah[2][4];
            #pragma unroll
            for (int mt = 0; mt < 2; mt++) {
                int r = mg * 32 + mt * 16 + (ln & 15);
                int u = k2 * 2 + (ln >> 4);
                ldm4(buf + XA + swof(r, u, 128), ah[mt]);
            }
            u32 bh[4][4], bl[4][4];
            #pragma unroll
            for (int p = 0; p < 4; p++) {
                int r = ng * 64 + p * 16 + (ln & 7) + ((ln & 16) >> 1);
                int u = k2 * 2 + ((ln >> 3) & 1);
                ldm4(buf + XWH + swof(r, u, 128), bh[p]);
                ldm4(buf + XWL + swof(r, u, 128), bl[p]);
            }
            #pragma unroll
            for (int mt = 0; mt < 2; mt++)
                #pragma unroll
                for (int nt = 0; nt < 8; nt++) {
                    const int p = nt >> 1, o = (nt & 1) * 2;
                    mma_fp16(c[mt][nt], ah[mt], bh[p][o], bh[p][o + 1]);
                    mma_fp16(c[mt][nt], ah[mt], bl[p][o], bl[p][o + 1]);
                }
        }
        __syncthreads();
    }

    #pragma unroll
    for (int mt = 0; mt < 2; mt++) {
        const int row = m0 + mg * 32 + mt * 16 + (ln >> 2);
        #pragma unroll
        for (int nt = 0; nt < 8; nt++) {
            const int col = ng * 64 + nt * 8 + (ln & 3) * 2;
            float b0 = bias_s[col], b1 = bias_s[col + 1];
            *(float2*)(g_xg + (size_t)row * kG + n0 + col)       = make_float2(c[mt][nt][0] + b0, c[mt][nt][1] + b1);
            *(float2*)(g_xg + (size_t)(row + 8) * kG + n0 + col) = make_float2(c[mt][nt][2] + b0, c[mt][nt][3] + b1);
        }
    }
}

// ============================================================================
// Phase 2: persistent recurrence. 128 blocks x 512 threads, 1 block/SM.
// Block jblk: C[32 gate-rows, 64 batch] = Wslice @ h^T (rows = g*8 + jl, j0 = jblk*8).
// W hi+lo resident in smem (128 KB). h fp16 streamed per step: 4 chunks K=256.
// 16 warps: mg(2) x ng(4) x ks(2). Warp tile 16x16, K-half 512. c-state in regs.
// ============================================================================
static constexpr int RWH   = 0;                 // 64 KB
static constexpr int RWL   = 65536;             // 64 KB
static constexpr int RBUF  = 131072;            // 2 x 32 KB h chunk buffers
static constexpr int RRED  = RBUF + 65536;      // 196608 : 2*32*68 fp32 = 17408
static constexpr int RC_SMEM = RRED + 17408;    // 214016

__global__ __launch_bounds__(512, 1) void lstm_tc(
    const float* __restrict__ c0, float* __restrict__ out)
{
    extern __shared__ char sm[];
    const u32 sb  = smem_u32(sm);
    const int tid = threadIdx.x;
    const int wid = tid >> 5;
    const int ln  = tid & 31;
    const int jblk = blockIdx.x;
    const int j0   = jblk * 8;
    const int mg = wid & 1, ng = (wid >> 1) & 3, ks = wid >> 3;
    float* red = (float*)(sm + RRED);

    // resident W load (hi + lo), swizzled, stride 2048 B
    #pragma unroll
    for (int rep = 0; rep < 8; rep++) {
        int idx = tid + rep * 512;       // 0..4095 : 32 rows x 128 units
        int r = idx >> 7, u = idx & 127;
        u32 sw = swof(r, u, 2048);
        cp16(sb + RWH + sw, (const char*)g_wp_h + ((size_t)(jblk * 32 + r) * kH + u * 8) * 2);
        cp16(sb + RWL + sw, (const char*)g_wp_l + ((size_t)(jblk * 32 + r) * kH + u * 8) * 2);
    }
    cp_commit();

    // cell ownership: b = tid>>3, jl = tid&7 ; c-state lives in a register
    const int cb  = tid >> 3;
    const int cjl = tid & 7;
    float creg = c0[(size_t)cb * kH + j0 + cjl];

    cp_wait0();
    __syncthreads();

    for (int t = 0; t < kT; t++) {
        const __half* hsrc = g_h16[t & 1];

        // x-gates prefetch (global latency hidden under staging + MMA)
        float xgv[4];
        {
            const float* xp = g_xg + ((size_t)t * kB + cb) * kG + j0 + cjl;
            #pragma unroll
            for (int g = 0; g < 4; g++) xgv[g] = xp[g * kH];
        }

        auto stage = [&](int ch, u32 buf) {
            #pragma unroll
            for (int rep = 0; rep < 4; rep++) {
                int idx = tid + rep * 512;   // 0..2047 : 64 rows x 32 units
                int r = idx >> 5, u = idx & 31;
                cp16(buf + swof(r, u, 512),
                     (const char*)hsrc + ((size_t)r * kH + ch * 256 + u * 8) * 2);
            }
            cp_commit();
        };

        float cc[2][4];
        #pragma unroll
        for (int i = 0; i < 2; i++)
            #pragma unroll
            for (int q = 0; q < 4; q++) cc[i][q] = 0.f;

        stage(0, sb + RBUF);
        for (int ch = 0; ch < 4; ch++) {
            const u32 buf = sb + RBUF + (ch & 1) * 32768;
            if (ch < 3) { stage(ch + 1, sb + RBUF + ((ch + 1) & 1) * 32768); cp_wait1(); }
            else cp_wait0();
            __syncthreads();
            #pragma unroll
            for (int k2 = 0; k2 < 8; k2++) {
                const int gk = ch * 16 + ks * 8 + k2;     // global k16 index 0..63
                u32 ah[4], al[4], bb[4];
                {
                    int r = mg * 16 + (ln & 15);
                    int u = gk * 2 + (ln >> 4);
                    ldm4(sb + RWH + swof(r, u, 2048), ah);
                    ldm4(sb + RWL + swof(r, u, 2048), al);
                }
                {
                    int r = ng * 16 + (ln & 7) + ((ln & 16) >> 1);
                    int u = (ks * 8 + k2) * 2 + ((ln >> 3) & 1);
                    ldm4(buf + swof(r, u, 512), bb);
                }
                mma_fp16(cc[0], ah, bb[0], bb[1]);
                mma_fp16(cc[1], ah, bb[2], bb[3]);
                mma_fp16(cc[0], al, bb[0], bb[1]);
                mma_fp16(cc[1], al, bb[2], bb[3]);
            }
            __syncthreads();
        }

        // C frags -> red[ks][row][col]
        {
            float* rp = red + ks * (32 * 68);
            const int r0  = mg * 16 + (ln >> 2);
            const int col = ng * 16 + (ln & 3) * 2;
            *(float2*)(rp + r0 * 68 + col)           = make_float2(cc[0][0], cc[0][1]);
            *(float2*)(rp + (r0 + 8) * 68 + col)     = make_float2(cc[0][2], cc[0][3]);
            *(float2*)(rp + r0 * 68 + col + 8)       = make_float2(cc[1][0], cc[1][1]);
            *(float2*)(rp + (r0 + 8) * 68 + col + 8) = make_float2(cc[1][2], cc[1][3]);
        }
        __syncthreads();

        // fused cell update (c-state in register)
        {
            float gv[4];
            #pragma unroll
            for (int g = 0; g < 4; g++) {
                const int row = g * 8 + cjl;
                gv[g] = red[row * 68 + cb] + red[32 * 68 + row * 68 + cb] + xgv[g];
            }
            float gi = sigf(gv[0]);
            float gf = sigf(gv[1]);
            float gg = tanh_fast(gv[2]);
            float go = sigf(gv[3]);
            creg = gf * creg + gi * gg;
            float hy = go * tanh_fast(creg);
            out[((size_t)t * kB + cb) * kH + j0 + cjl] = hy;
            g_h16[(t & 1) ^ 1][(size_t)cb * kH + j0 + cjl] = __float2half_rn(hy);
        }

        // grid barrier between steps
        if (t < kT - 1) {
            __threadfence();
            __syncthreads();
            if (tid == 0) {
                unsigned a = atomicAdd(&g_cnt, 1u) + 1u;
                if (a == (unsigned)(t + 1) * RBLK) {
                    __threadfence();
                    atomicExch(&g_rel, (unsigned)(t + 1));
                } else {
                    while (*((volatile unsigned*)&g_rel) < (unsigned)(t + 1)) { }
                }
            }
            __syncthreads();
        }
    }

    // final cell state
    out[(size_t)kT * kB * kH + (size_t)cb * kH + j0 + cjl] = creg;
}

// ============================================================================
extern "C" void kernel_launch(void* const* d_in, const int* in_sizes, int n_in,
                              void* d_out, int out_size) {
    const float* x   = (const float*)d_in[0];
    const float* h0  = (const float*)d_in[1];
    const float* c0  = (const float*)d_in[2];
    const float* wih = (const float*)d_in[3];
    const float* whh = (const float*)d_in[4];
    const float* bih = (const float*)d_in[5];
    const float* bhh = (const float*)d_in[6];
    float* out = (float*)d_out;

    static bool attr_set = false;
    if (!attr_set) {
        cudaFuncSetAttribute(xgates_tc, cudaFuncAttributeMaxDynamicSharedMemorySize, XG_SMEM);
        cudaFuncSetAttribute(lstm_tc,   cudaFuncAttributeMaxDynamicSharedMemorySize, RC_SMEM);
        attr_set = true;
    }

    init_kernel<<<1, 1>>>();
    split_x16<<<4096, 256>>>(x, kT * kB * kH);
    split_wih<<<1024, 256>>>(wih, kG * kH);
    split_h0_16<<<64, 256>>>(h0, kB * kH);
    pack_whh16<<<1024, 256>>>(whh);
    xgates_tc<<<dim3(kG / 128, (kT * kB) / 128), 256, XG_SMEM>>>(bih, bhh);
    lstm_tc<<<RBLK, 512, RC_SMEM>>>(c0, out);
}

// round 7
// speedup vs baseline: 8.1435x; 1.3433x over previous
#include <cuda_runtime.h>
#include <cuda_fp16.h>
#include <math.h>
#include <stdint.h>

typedef uint32_t u32;

static constexpr int kT = 512;
static constexpr int kB = 64;
static constexpr int kH = 1024;
static constexpr int kG = 4096;
static constexpr int RBLK = 128;

// ---------------- global scratch ----------------
__device__ float  g_xg[(size_t)kT * kB * kG];      // x-gates fp32 (incl. biases)
__device__ __half g_x16[(size_t)kT * kB * kH];     // x fp16
__device__ __half g_wih[(size_t)kG * kH];          // W_ih fp16
__device__ __half g_wp[(size_t)kG * kH];           // W_hh fp16 packed [jblk][row][k]
__device__ __half g_h16[2][kB * kH];               // h fp16, double buffered [b][k]
__device__ unsigned g_cnt, g_rel;

// ---------------- PTX helpers ----------------
__device__ __forceinline__ u32 smem_u32(const void* p) {
    u32 a;
    asm("{ .reg .u64 t; cvta.to.shared.u64 t, %1; cvt.u32.u64 %0, t; }" : "=r"(a) : "l"(p));
    return a;
}
__device__ __forceinline__ void cp16(u32 dst, const void* src) {
    asm volatile("cp.async.cg.shared.global [%0], [%1], 16;" :: "r"(dst), "l"(src) : "memory");
}
__device__ __forceinline__ void cp_commit() { asm volatile("cp.async.commit_group;" ::: "memory"); }
__device__ __forceinline__ void cp_wait0()  { asm volatile("cp.async.wait_group 0;" ::: "memory"); }
__device__ __forceinline__ void cp_wait1()  { asm volatile("cp.async.wait_group 1;" ::: "memory"); }

__device__ __forceinline__ void ldm4(u32 a, u32* r) {
    asm volatile("ldmatrix.sync.aligned.m8n8.x4.shared.b16 {%0,%1,%2,%3}, [%4];"
                 : "=r"(r[0]), "=r"(r[1]), "=r"(r[2]), "=r"(r[3]) : "r"(a));
}
__device__ __forceinline__ void mma_fp16(float* c, const u32* a, u32 b0, u32 b1) {
    asm volatile("mma.sync.aligned.m16n8k16.row.col.f32.f16.f16.f32 "
                 "{%0,%1,%2,%3}, {%4,%5,%6,%7}, {%8,%9}, {%0,%1,%2,%3};"
                 : "+f"(c[0]), "+f"(c[1]), "+f"(c[2]), "+f"(c[3])
                 : "r"(a[0]), "r"(a[1]), "r"(a[2]), "r"(a[3]), "r"(b0), "r"(b1));
}
// swizzled byte offset: row r, 16B-unit u, row stride bytes (multiple of 128)
__device__ __forceinline__ u32 swof(int r, int u, int stride) {
    return (u32)(r * stride + ((u >> 3) << 7) + (((u ^ r) & 7) << 4));
}

__device__ __forceinline__ float sigf(float x) { return 1.f / (1.f + __expf(-x)); }
__device__ __forceinline__ float tanh_fast(float x) {
    float t = 2.f / (__expf(2.f * fabsf(x)) + 1.f);
    float r = 1.f - t;
    return x >= 0.f ? r : -r;
}

// ---------------- prep kernels ----------------
__global__ void init_kernel() { g_cnt = 0u; g_rel = 0u; }

__global__ void split_x16(const float* __restrict__ s, int n) {
    for (int i = blockIdx.x * blockDim.x + threadIdx.x; i < n; i += gridDim.x * blockDim.x)
        g_x16[i] = __float2half_rn(s[i]);
}
__global__ void split_wih(const float* __restrict__ s, int n) {
    for (int i = blockIdx.x * blockDim.x + threadIdx.x; i < n; i += gridDim.x * blockDim.x)
        g_wih[i] = __float2half_rn(s[i]);
}
__global__ void split_h0_16(const float* __restrict__ s, int n) {
    for (int i = blockIdx.x * blockDim.x + threadIdx.x; i < n; i += gridDim.x * blockDim.x)
        g_h16[0][i] = __float2half_rn(s[i]);
}
// g_wp[(jblk*32 + row)*1024 + k], row = g*8 + jl, src row = g*1024 + jblk*8 + jl
__global__ void pack_whh16(const float* __restrict__ whh) {
    const int n = kG * kH;
    for (int i = blockIdx.x * blockDim.x + threadIdx.x; i < n; i += gridDim.x * blockDim.x) {
        int k    = i & 1023;
        int row  = (i >> 10) & 31;
        int jblk = i >> 15;
        int g = row >> 3, jl = row & 7;
        g_wp[i] = __float2half_rn(whh[(size_t)(g * kH + jblk * 8 + jl) * kH + k]);
    }
}

// ============================================================================
// Phase 1: x-gates GEMM (fp16 HMMA, single product). C = x @ Wih^T + biases.
// 128x128 tile, 256 thr, warp tile 32x64. K chunks of 64, double buffered.
// ============================================================================
static constexpr int XA   = 0;            // x fp16 (16 KB)
static constexpr int XWH  = 16384;        // W (16 KB)
static constexpr int XBUFSZ = 32768;
static constexpr int XBIAS  = 2 * XBUFSZ;
static constexpr int XG_SMEM = XBIAS + 512;

__global__ __launch_bounds__(256, 2) void xgates_tc(
    const float* __restrict__ bih, const float* __restrict__ bhh)
{
    extern __shared__ char sm[];
    const u32 sb  = smem_u32(sm);
    const int tid = threadIdx.x;
    const int wid = tid >> 5;
    const int ln  = tid & 31;
    const int mg  = wid & 3;
    const int ng  = wid >> 2;
    const int n0  = blockIdx.x * 128;
    const int m0  = blockIdx.y * 128;
    float* bias_s = (float*)(sm + XBIAS);

    if (tid < 128) bias_s[tid] = bih[n0 + tid] + bhh[n0 + tid];

    auto stage = [&](int ch, u32 buf) {
        #pragma unroll
        for (int rep = 0; rep < 4; rep++) {
            int idx = tid + rep * 256;     // 0..1023 : 128 rows x 8 units
            int r = idx >> 3, u = idx & 7;
            u32 sw = swof(r, u, 128);
            cp16(buf + XA  + sw, (const char*)g_x16 + ((size_t)(m0 + r) * kH + ch * 64 + u * 8) * 2);
            cp16(buf + XWH + sw, (const char*)g_wih + ((size_t)(n0 + r) * kH + ch * 64 + u * 8) * 2);
        }
        cp_commit();
    };

    float c[2][8][4];
    #pragma unroll
    for (int i = 0; i < 2; i++)
        #pragma unroll
        for (int j = 0; j < 8; j++)
            #pragma unroll
            for (int q = 0; q < 4; q++) c[i][j][q] = 0.f;

    stage(0, sb);
    for (int ch = 0; ch < 16; ch++) {
        const u32 buf = sb + (ch & 1) * XBUFSZ;
        if (ch < 15) { stage(ch + 1, sb + ((ch + 1) & 1) * XBUFSZ); cp_wait1(); }
        else cp_wait0();
        __syncthreads();
        #pragma unroll
        for (int k2 = 0; k2 < 4; k2++) {
            u32 ah[2][4];
            #pragma unroll
            for (int mt = 0; mt < 2; mt++) {
                int r = mg * 32 + mt * 16 + (ln & 15);
                int u = k2 * 2 + (ln >> 4);
                ldm4(buf + XA + swof(r, u, 128), ah[mt]);
            }
            u32 bh[4][4];
            #pragma unroll
            for (int p = 0; p < 4; p++) {
                int r = ng * 64 + p * 16 + (ln & 7) + ((ln & 16) >> 1);
                int u = k2 * 2 + ((ln >> 3) & 1);
                ldm4(buf + XWH + swof(r, u, 128), bh[p]);
            }
            #pragma unroll
            for (int mt = 0; mt < 2; mt++)
                #pragma unroll
                for (int nt = 0; nt < 8; nt++) {
                    const int p = nt >> 1, o = (nt & 1) * 2;
                    mma_fp16(c[mt][nt], ah[mt], bh[p][o], bh[p][o + 1]);
                }
        }
        __syncthreads();
    }

    #pragma unroll
    for (int mt = 0; mt < 2; mt++) {
        const int row = m0 + mg * 32 + mt * 16 + (ln >> 2);
        #pragma unroll
        for (int nt = 0; nt < 8; nt++) {
            const int col = ng * 64 + nt * 8 + (ln & 3) * 2;
            float b0 = bias_s[col], b1 = bias_s[col + 1];
            *(float2*)(g_xg + (size_t)row * kG + n0 + col)       = make_float2(c[mt][nt][0] + b0, c[mt][nt][1] + b1);
            *(float2*)(g_xg + (size_t)(row + 8) * kG + n0 + col) = make_float2(c[mt][nt][2] + b0, c[mt][nt][3] + b1);
        }
    }
}

// ============================================================================
// Phase 2: persistent recurrence. 128 blocks x 512 threads, 1 block/SM.
// Block jblk: C[32 gate-rows, 64 batch] = Wslice @ h^T. W fp16 resident (64 KB).
// h fp16 streamed: 2 chunks of K=512 (64 KB each), both staged up-front.
// 16 warps: mg(2) x ng(4) x ks(2). Warp tile 16x16, K-half 512. c-state in regs.
// ============================================================================
static constexpr int RWH   = 0;                 // 64 KB resident W
static constexpr int RBUF  = 65536;             // 2 x 64 KB h chunk buffers
static constexpr int RRED  = RBUF + 131072;     // 196608 : 2*32*68 fp32 = 17408
static constexpr int RC_SMEM = RRED + 17408;    // 214016

__global__ __launch_bounds__(512, 1) void lstm_tc(
    const float* __restrict__ c0, float* __restrict__ out)
{
    extern __shared__ char sm[];
    const u32 sb  = smem_u32(sm);
    const int tid = threadIdx.x;
    const int wid = tid >> 5;
    const int ln  = tid & 31;
    const int jblk = blockIdx.x;
    const int j0   = jblk * 8;
    const int mg = wid & 1, ng = (wid >> 1) & 3, ks = wid >> 3;
    float* red = (float*)(sm + RRED);

    // resident W load: 32 rows x 128 units, swizzled, stride 2048 B
    #pragma unroll
    for (int rep = 0; rep < 8; rep++) {
        int idx = tid + rep * 512;       // 0..4095
        int r = idx >> 7, u = idx & 127;
        cp16(sb + RWH + swof(r, u, 2048),
             (const char*)g_wp + ((size_t)(jblk * 32 + r) * kH + u * 8) * 2);
    }
    cp_commit();

    // cell ownership: b = tid>>3, jl = tid&7 ; c-state in a register
    const int cb  = tid >> 3;
    const int cjl = tid & 7;
    float creg = c0[(size_t)cb * kH + j0 + cjl];

    cp_wait0();
    __syncthreads();

    for (int t = 0; t < kT; t++) {
        const __half* hsrc = g_h16[t & 1];

        // x-gates prefetch (global latency hidden under staging + MMA)
        float xgv[4];
        {
            const float* xp = g_xg + ((size_t)t * kB + cb) * kG + j0 + cjl;
            #pragma unroll
            for (int g = 0; g < 4; g++) xgv[g] = xp[g * kH];
        }

        // stage BOTH chunks (separate commit groups): 64 rows x 64 units each
        #pragma unroll
        for (int ch = 0; ch < 2; ch++) {
            const u32 buf = sb + RBUF + ch * 65536;
            #pragma unroll
            for (int rep = 0; rep < 8; rep++) {
                int idx = tid + rep * 512;   // 0..4095
                int r = idx >> 6, u = idx & 63;
                cp16(buf + swof(r, u, 1024),
                     (const char*)hsrc + ((size_t)r * kH + ch * 512 + u * 8) * 2);
            }
            cp_commit();
        }

        float cc[2][4];
        #pragma unroll
        for (int i = 0; i < 2; i++)
            #pragma unroll
            for (int q = 0; q < 4; q++) cc[i][q] = 0.f;

        #pragma unroll
        for (int ch = 0; ch < 2; ch++) {
            if (ch == 0) cp_wait1(); else cp_wait0();
            __syncthreads();
            const u32 buf = sb + RBUF + ch * 65536;
            #pragma unroll
            for (int k2 = 0; k2 < 16; k2++) {
                const int gk = ch * 32 + ks * 16 + k2;     // global k16 index 0..63
                u32 aa[4], bb[4];
                {
                    int r = mg * 16 + (ln & 15);
                    int u = gk * 2 + (ln >> 4);
                    ldm4(sb + RWH + swof(r, u, 2048), aa);
                }
                {
                    int r = ng * 16 + (ln & 7) + ((ln & 16) >> 1);
                    int u = (ks * 16 + k2) * 2 + ((ln >> 3) & 1);
                    ldm4(buf + swof(r, u, 1024), bb);
                }
                mma_fp16(cc[0], aa, bb[0], bb[1]);
                mma_fp16(cc[1], aa, bb[2], bb[3]);
            }
        }

        // C frags -> red[ks][row][col]
        {
            float* rp = red + ks * (32 * 68);
            const int r0  = mg * 16 + (ln >> 2);
            const int col = ng * 16 + (ln & 3) * 2;
            *(float2*)(rp + r0 * 68 + col)           = make_float2(cc[0][0], cc[0][1]);
            *(float2*)(rp + (r0 + 8) * 68 + col)     = make_float2(cc[0][2], cc[0][3]);
            *(float2*)(rp + r0 * 68 + col + 8)       = make_float2(cc[1][0], cc[1][1]);
            *(float2*)(rp + (r0 + 8) * 68 + col + 8) = make_float2(cc[1][2], cc[1][3]);
        }
        __syncthreads();

        // fused cell update (c-state in register)
        {
            float gv[4];
            #pragma unroll
            for (int g = 0; g < 4; g++) {
                const int row = g * 8 + cjl;
                gv[g] = red[row * 68 + cb] + red[32 * 68 + row * 68 + cb] + xgv[g];
            }
            float gi = sigf(gv[0]);
            float gf = sigf(gv[1]);
            float gg = tanh_fast(gv[2]);
            float go = sigf(gv[3]);
            creg = gf * creg + gi * gg;
            float hy = go * tanh_fast(creg);
            out[((size_t)t * kB + cb) * kH + j0 + cjl] = hy;
            g_h16[(t & 1) ^ 1][(size_t)cb * kH + j0 + cjl] = __float2half_rn(hy);
        }

        // grid barrier between steps
        if (t < kT - 1) {
            __threadfence();
            __syncthreads();
            if (tid == 0) {
                unsigned a = atomicAdd(&g_cnt, 1u) + 1u;
                if (a == (unsigned)(t + 1) * RBLK) {
                    __threadfence();
                    atomicExch(&g_rel, (unsigned)(t + 1));
                } else {
                    while (*((volatile unsigned*)&g_rel) < (unsigned)(t + 1)) { }
                }
            }
            __syncthreads();
        }
    }

    // final cell state
    out[(size_t)kT * kB * kH + (size_t)cb * kH + j0 + cjl] = creg;
}

// ============================================================================
extern "C" void kernel_launch(void* const* d_in, const int* in_sizes, int n_in,
                              void* d_out, int out_size) {
    const float* x   = (const float*)d_in[0];
    const float* h0  = (const float*)d_in[1];
    const float* c0  = (const float*)d_in[2];
    const float* wih = (const float*)d_in[3];
    const float* whh = (const float*)d_in[4];
    const float* bih = (const float*)d_in[5];
    const float* bhh = (const float*)d_in[6];
    float* out = (float*)d_out;

    static bool attr_set = false;
    if (!attr_set) {
        cudaFuncSetAttribute(xgates_tc, cudaFuncAttributeMaxDynamicSharedMemorySize, XG_SMEM);
        cudaFuncSetAttribute(lstm_tc,   cudaFuncAttributeMaxDynamicSharedMemorySize, RC_SMEM);
        attr_set = true;
    }

    init_kernel<<<1, 1>>>();
    split_x16<<<4096, 256>>>(x, kT * kB * kH);
    split_wih<<<1024, 256>>>(wih, kG * kH);
    split_h0_16<<<64, 256>>>(h0, kB * kH);
    pack_whh16<<<1024, 256>>>(whh);
    xgates_tc<<<dim3(kG / 128, (kT * kB) / 128), 256, XG_SMEM>>>(bih, bhh);
    lstm_tc<<<RBLK, 512, RC_SMEM>>>(c0, out);
}